// round 1
// baseline (speedup 1.0000x reference)
#include <cuda_runtime.h>
#include <math.h>

#define B_   2
#define S_   2048
#define D_   1024
#define H_   16
#define DH_  64
#define WIN_ 256
#define M_   (B_*S_)        // 4096

// Scratch (static device globals — no allocation)
__device__ float g_q [B_*H_*S_*DH_];
__device__ float g_k [B_*H_*S_*DH_];
__device__ float g_v [B_*H_*S_*DH_];
__device__ float g_ao[B_*S_*D_];

// ---------------------------------------------------------------------------
// SGEMM: C[M,N] = A[M,K] @ W[K,N] + bias, optional scale, optional QKV layout
// 128x128 block tile, BK=8, 256 threads, 8x8 per-thread microtile.
// MODE 0: plain row-major store. MODE 1: store to [B,H,S,DH] (transposed heads).
// ---------------------------------------------------------------------------
template<int MODE>
__global__ __launch_bounds__(256) void sgemm_kernel(
    const float* __restrict__ A, const float* __restrict__ W,
    const float* __restrict__ bias, float* __restrict__ C,
    float scale)
{
    const int K = D_, N = D_;
    __shared__ float As[8][128];   // transposed A tile
    __shared__ float Bs[8][128];

    const int tid  = threadIdx.x;
    const int bm   = blockIdx.y << 7;
    const int bn   = blockIdx.x << 7;
    const int arow = tid >> 1, acol = (tid & 1) << 2;
    const int brow = tid >> 5, bcol = (tid & 31) << 2;
    const int tx   = tid & 15, ty   = tid >> 4;

    float acc[8][8];
#pragma unroll
    for (int i = 0; i < 8; i++)
#pragma unroll
        for (int j = 0; j < 8; j++) acc[i][j] = 0.f;

    const float* Aptr = A + (size_t)(bm + arow) * K + acol;
    const float* Wptr = W + (size_t)brow * N + bn + bcol;

    for (int k0 = 0; k0 < K; k0 += 8) {
        float4 av = *(const float4*)(Aptr + k0);
        As[acol + 0][arow] = av.x;
        As[acol + 1][arow] = av.y;
        As[acol + 2][arow] = av.z;
        As[acol + 3][arow] = av.w;
        float4 bv = *(const float4*)(Wptr + (size_t)k0 * N);
        *(float4*)&Bs[brow][bcol] = bv;
        __syncthreads();
#pragma unroll
        for (int kk = 0; kk < 8; kk++) {
            float a[8], b[8];
            *(float4*)(a)     = *(const float4*)&As[kk][ty << 2];
            *(float4*)(a + 4) = *(const float4*)&As[kk][64 + (ty << 2)];
            *(float4*)(b)     = *(const float4*)&Bs[kk][tx << 2];
            *(float4*)(b + 4) = *(const float4*)&Bs[kk][64 + (tx << 2)];
#pragma unroll
            for (int i = 0; i < 8; i++)
#pragma unroll
                for (int j = 0; j < 8; j++)
                    acc[i][j] += a[i] * b[j];
        }
        __syncthreads();
    }

    // Epilogue: bias + scale; float4 stores
#pragma unroll
    for (int i = 0; i < 8; i++) {
        int gm = bm + ((i < 4) ? (ty * 4 + i) : (64 + ty * 4 + i - 4));
#pragma unroll
        for (int jh = 0; jh < 2; jh++) {
            int gn = bn + ((jh == 0) ? (tx * 4) : (64 + tx * 4));
            float4 o;
            o.x = (acc[i][jh * 4 + 0] + bias[gn + 0]) * scale;
            o.y = (acc[i][jh * 4 + 1] + bias[gn + 1]) * scale;
            o.z = (acc[i][jh * 4 + 2] + bias[gn + 2]) * scale;
            o.w = (acc[i][jh * 4 + 3] + bias[gn + 3]) * scale;
            if (MODE == 0) {
                *(float4*)(C + (size_t)gm * N + gn) = o;
            } else {
                int bb = gm >> 11;        // / S_
                int ss = gm & (S_ - 1);
                int hh = gn >> 6;         // / DH_
                int dd = gn & (DH_ - 1);  // multiple of 4, <= 60
                *(float4*)(C + ((((size_t)bb * H_ + hh) * S_ + ss) << 6) + dd) = o;
            }
        }
    }
}

// ---------------------------------------------------------------------------
// Windowed attention: one block per (b, h, 64-query tile). 256 threads.
// Online softmax over up to 5 key chunks of 64 (window 256 + causal).
// Thread mapping (scores): rows {rg+16i}, cols {cg+16j}; (AV): dims {cg*4..+3}.
// Q was pre-scaled by 1/8 in the projection epilogue.
// ---------------------------------------------------------------------------
#define AT_ST 68    // smem row stride: float4-aligned, conflict-free patterns

__global__ __launch_bounds__(256) void attn_kernel(
    const float* __restrict__ Q, const float* __restrict__ K,
    const float* __restrict__ V, float* __restrict__ O)
{
    extern __shared__ float sm[];
    float* Qs = sm;                    // [64][AT_ST]
    float* Ks = Qs + 64 * AT_ST;
    float* Vs = Ks + 64 * AT_ST;
    float* Ps = Vs + 64 * AT_ST;       // [row][key]

    const int tid = threadIdx.x;
    const int q0  = blockIdx.x << 6;
    const int h   = blockIdx.y;
    const int b   = blockIdx.z;
    const size_t bh = ((size_t)b * H_ + h) * S_;

    const int rg = tid >> 4;   // 0..15
    const int cg = tid & 15;   // 0..15

    // Load Q tile (coalesced float4)
    {
        const float* src = Q + (bh + q0) * DH_;
#pragma unroll
        for (int t = 0; t < 4; t++) {
            int i   = tid + (t << 8);
            int row = i >> 4;
            int c4  = (i & 15) << 2;
            *(float4*)(Qs + row * AT_ST + c4) = *(const float4*)(src + (row << 6) + c4);
        }
    }

    float m[4], l[4], acc[4][4];
#pragma unroll
    for (int i = 0; i < 4; i++) {
        m[i] = -1e30f; l[i] = 0.f;
#pragma unroll
        for (int j = 0; j < 4; j++) acc[i][j] = 0.f;
    }

    const int kstart = (q0 - WIN_) > 0 ? (q0 - WIN_) : 0;
    for (int kb = kstart; kb <= q0; kb += 64) {
        __syncthreads();   // previous chunk fully consumed
        {
            const float* ksrc = K + (bh + kb) * DH_;
            const float* vsrc = V + (bh + kb) * DH_;
#pragma unroll
            for (int t = 0; t < 4; t++) {
                int i   = tid + (t << 8);
                int row = i >> 4;
                int c4  = (i & 15) << 2;
                *(float4*)(Ks + row * AT_ST + c4) = *(const float4*)(ksrc + (row << 6) + c4);
                *(float4*)(Vs + row * AT_ST + c4) = *(const float4*)(vsrc + (row << 6) + c4);
            }
        }
        __syncthreads();

        // ---- scores s[i][j] = q[rg+16i] . k[cg+16j] ----
        float s[4][4];
#pragma unroll
        for (int i = 0; i < 4; i++)
#pragma unroll
            for (int j = 0; j < 4; j++) s[i][j] = 0.f;

#pragma unroll
        for (int kk = 0; kk < 64; kk += 4) {
            float4 qv[4], kv[4];
#pragma unroll
            for (int i = 0; i < 4; i++)
                qv[i] = *(const float4*)(Qs + (rg + 16 * i) * AT_ST + kk);
#pragma unroll
            for (int j = 0; j < 4; j++)
                kv[j] = *(const float4*)(Ks + (cg + 16 * j) * AT_ST + kk);
#pragma unroll
            for (int i = 0; i < 4; i++)
#pragma unroll
                for (int j = 0; j < 4; j++)
                    s[i][j] += qv[i].x * kv[j].x + qv[i].y * kv[j].y
                             + qv[i].z * kv[j].z + qv[i].w * kv[j].w;
        }

        // ---- mask + online softmax (row stats shared across 16 lanes) ----
#pragma unroll
        for (int i = 0; i < 4; i++) {
            int qi = q0 + rg + 16 * i;
            float mx = -1e30f;
#pragma unroll
            for (int j = 0; j < 4; j++) {
                int kj = kb + cg + 16 * j;
                bool valid = (kj <= qi) && ((qi - kj) <= WIN_);
                if (!valid) s[i][j] = -1e30f;
                mx = fmaxf(mx, s[i][j]);
            }
#pragma unroll
            for (int off = 8; off >= 1; off >>= 1)
                mx = fmaxf(mx, __shfl_xor_sync(0xffffffffu, mx, off, 16));
            float mn   = fmaxf(m[i], mx);
            float corr = __expf(m[i] - mn);
            float ps = 0.f;
#pragma unroll
            for (int j = 0; j < 4; j++) {
                float p = __expf(s[i][j] - mn);
                s[i][j] = p;
                ps += p;
            }
#pragma unroll
            for (int off = 8; off >= 1; off >>= 1)
                ps += __shfl_xor_sync(0xffffffffu, ps, off, 16);
            l[i] = l[i] * corr + ps;
            m[i] = mn;
#pragma unroll
            for (int j = 0; j < 4; j++) acc[i][j] *= corr;
#pragma unroll
            for (int j = 0; j < 4; j++)
                Ps[(rg + 16 * i) * AT_ST + cg + 16 * j] = s[i][j];
        }
        __syncthreads();

        // ---- AV: acc[i][d] += sum_jk P[row][jk] * V[jk][d], d = cg*4..+3 ----
#pragma unroll 4
        for (int jk = 0; jk < 64; jk++) {
            float4 vv = *(const float4*)(Vs + jk * AT_ST + (cg << 2));
            float pv[4];
#pragma unroll
            for (int i = 0; i < 4; i++)
                pv[i] = Ps[(rg + 16 * i) * AT_ST + jk];
#pragma unroll
            for (int i = 0; i < 4; i++) {
                acc[i][0] += pv[i] * vv.x;
                acc[i][1] += pv[i] * vv.y;
                acc[i][2] += pv[i] * vv.z;
                acc[i][3] += pv[i] * vv.w;
            }
        }
    }

    // ---- normalize + store in [B,S,D] layout ----
#pragma unroll
    for (int i = 0; i < 4; i++) {
        int row = rg + 16 * i;
        float inv = 1.f / l[i];
        float4 o = make_float4(acc[i][0] * inv, acc[i][1] * inv,
                               acc[i][2] * inv, acc[i][3] * inv);
        *(float4*)(O + ((size_t)b * S_ + q0 + row) * D_ + (h << 6) + (cg << 2)) = o;
    }
}

// ---------------------------------------------------------------------------
extern "C" void kernel_launch(void* const* d_in, const int* in_sizes, int n_in,
                              void* d_out, int out_size)
{
    const float* x  = (const float*)d_in[0];
    const float* wq = (const float*)d_in[1];
    const float* bq = (const float*)d_in[2];
    const float* wk = (const float*)d_in[3];
    const float* bk = (const float*)d_in[4];
    const float* wv = (const float*)d_in[5];
    const float* bv = (const float*)d_in[6];
    const float* wo = (const float*)d_in[7];
    const float* bo = (const float*)d_in[8];
    float* out = (float*)d_out;

    float *qp, *kp, *vp, *aop;
    cudaGetSymbolAddress((void**)&qp,  g_q);
    cudaGetSymbolAddress((void**)&kp,  g_k);
    cudaGetSymbolAddress((void**)&vp,  g_v);
    cudaGetSymbolAddress((void**)&aop, g_ao);

    dim3 gg(D_ / 128, M_ / 128);   // (8, 32)

    // QKV projections (scale 1/sqrt(DH) folded into Q)
    sgemm_kernel<1><<<gg, 256>>>(x, wq, bq, qp, 0.125f);
    sgemm_kernel<1><<<gg, 256>>>(x, wk, bk, kp, 1.0f);
    sgemm_kernel<1><<<gg, 256>>>(x, wv, bv, vp, 1.0f);

    // Attention
    const int smem_bytes = 4 * 64 * AT_ST * (int)sizeof(float);   // 69632
    cudaFuncSetAttribute(attn_kernel,
                         cudaFuncAttributeMaxDynamicSharedMemorySize, smem_bytes);
    attn_kernel<<<dim3(S_ / 64, H_, B_), 256, smem_bytes>>>(qp, kp, vp, aop);

    // Output projection
    sgemm_kernel<0><<<gg, 256>>>(aop, wo, bo, out, 1.0f);
}

// round 3
// speedup vs baseline: 1.8333x; 1.8333x over previous
#include <cuda_runtime.h>
#include <cuda_bf16.h>
#include <math.h>
#include <cstdint>

#define B_   2
#define S_   2048
#define D_   1024
#define H_   16
#define DH_  64
#define WIN_ 256
#define M_   (B_*S_)        // 4096
#define K3_  3072           // split-GEMM K (hi|lo|hi)

// ---------------------------------------------------------------------------
// Scratch (static device globals — no allocation)
// ---------------------------------------------------------------------------
__device__ __align__(16) float g_q [B_*H_*S_*DH_];
__device__ __align__(16) float g_k [B_*H_*S_*DH_];
__device__ __align__(16) float g_v [B_*H_*S_*DH_];
__device__ __align__(16) __nv_bfloat16 g_xs [(size_t)M_*K3_];   // x split [M,3072]
__device__ __align__(16) __nv_bfloat16 g_ws [(size_t)3*D_*K3_]; // wq|wk|wv split [N,3072] each
__device__ __align__(16) __nv_bfloat16 g_wos[(size_t)D_*K3_];   // wo split
__device__ __align__(16) __nv_bfloat16 g_aos[(size_t)M_*K3_];   // attn out split

// ---------------------------------------------------------------------------
// helpers
// ---------------------------------------------------------------------------
__device__ __forceinline__ uint32_t smem_u32(const void* p) {
    uint32_t a;
    asm("{ .reg .u64 t; cvta.to.shared.u64 t, %1; cvt.u32.u64 %0, t; }"
        : "=r"(a) : "l"(p));
    return a;
}

#define CP16(sm_addr, gptr) \
    asm volatile("cp.async.cg.shared.global [%0], [%1], 16;" \
                 :: "r"(sm_addr), "l"(gptr) : "memory")
#define CP_COMMIT() asm volatile("cp.async.commit_group;" ::: "memory")

#define LDSM4(r, addr) \
    asm volatile("ldmatrix.sync.aligned.m8n8.x4.shared.b16 {%0,%1,%2,%3}, [%4];" \
        : "=r"((r)[0]), "=r"((r)[1]), "=r"((r)[2]), "=r"((r)[3]) : "r"(addr))

#define MMA16816(c, a, b) \
    asm volatile("mma.sync.aligned.m16n8k16.row.col.f32.bf16.bf16.f32 " \
        "{%0,%1,%2,%3}, {%4,%5,%6,%7}, {%8,%9}, {%0,%1,%2,%3};" \
        : "+f"((c)[0]), "+f"((c)[1]), "+f"((c)[2]), "+f"((c)[3]) \
        : "r"((a)[0]), "r"((a)[1]), "r"((a)[2]), "r"((a)[3]), \
          "r"((b)[0]), "r"((b)[1]))

__device__ __forceinline__ void split1(float f, unsigned short& h, unsigned short& l) {
    __nv_bfloat16 hb = __float2bfloat16(f);
    float r = f - __bfloat162float(hb);
    __nv_bfloat16 lb = __float2bfloat16(r);
    h = *reinterpret_cast<unsigned short*>(&hb);
    l = *reinterpret_cast<unsigned short*>(&lb);
}

// ---------------------------------------------------------------------------
// Prep: split x into [M,3072] = [hi | lo | hi]
// ---------------------------------------------------------------------------
__global__ __launch_bounds__(256) void split_x_kernel(
    const float4* __restrict__ x, unsigned short* __restrict__ out)
{
    int i = blockIdx.x * 256 + threadIdx.x;   // 0 .. M*D/4-1
    int r = i >> 8;                            // 256 float4 per row
    int c = i & 255;
    float4 f = x[i];
    ushort4 h, l;
    split1(f.x, h.x, l.x);
    split1(f.y, h.y, l.y);
    split1(f.z, h.z, l.z);
    split1(f.w, h.w, l.w);
    size_t base = (size_t)r * K3_ + (c << 2);
    *(ushort4*)(out + base)        = h;
    *(ushort4*)(out + base + 1024) = l;
    *(ushort4*)(out + base + 2048) = h;
}

// ---------------------------------------------------------------------------
// Prep: transpose W [K,N] -> [N,3072] = [hi | hi | lo]
// ---------------------------------------------------------------------------
__global__ __launch_bounds__(256) void split_w_t_kernel(
    const float* __restrict__ w, unsigned short* __restrict__ out)
{
    __shared__ float t[32][33];
    int tx = threadIdx.x, ty = threadIdx.y;
    int n0 = blockIdx.x * 32, k0 = blockIdx.y * 32;
#pragma unroll
    for (int j = 0; j < 32; j += 8)
        t[ty + j][tx] = w[(size_t)(k0 + ty + j) * D_ + n0 + tx];
    __syncthreads();
#pragma unroll
    for (int j = 0; j < 32; j += 8) {
        float f = t[tx][ty + j];
        unsigned short h, l;
        split1(f, h, l);
        size_t o = (size_t)(n0 + ty + j) * K3_ + k0 + tx;
        out[o]        = h;
        out[o + 1024] = h;
        out[o + 2048] = l;
    }
}

// ---------------------------------------------------------------------------
// HMMA GEMM: C[M,N] = A'[M,3072] @ B'[N,3072]^T  (bf16 mma.sync, fp32 accum)
// 128x128 CTA tile, BK=32, 4-stage cp.async pipeline, 8 warps (2x4), 64x32/warp.
// MODE 1: fused QKV (blockIdx.z selects weights/bias/out/scale), [B,H,S,DH] store.
// MODE 0: O projection, row-major store.
// ---------------------------------------------------------------------------
#define BK_      32
#define NITER_   (K3_ / BK_)       // 96
#define ROW_ST   80                // bytes per smem row (32 halfs + 8 pad)
#define A_BYTES  (128 * ROW_ST)    // 10240
#define STG_SZ   (2 * A_BYTES)     // 20480
#define GEMM_SMEM (4 * STG_SZ)     // 81920

template<int MODE>
__global__ __launch_bounds__(256) void hgemm(
    const __nv_bfloat16* __restrict__ A, const __nv_bfloat16* __restrict__ Bw,
    const float* __restrict__ b0, const float* __restrict__ b1, const float* __restrict__ b2,
    float* __restrict__ o0, float* __restrict__ o1, float* __restrict__ o2)
{
    extern __shared__ char smc[];
    const uint32_t sb = smem_u32(smc);
    const int tid  = threadIdx.x;
    const int lane = tid & 31;
    const int wid  = tid >> 5;
    const int wm   = wid >> 2;      // 0..1
    const int wn   = wid & 3;       // 0..3
    const int bm   = blockIdx.y << 7;
    const int bn   = blockIdx.x << 7;

    const __nv_bfloat16* Bp;
    const float* bias;
    float* Cp;
    float scale;
    if (MODE == 1) {
        int z = blockIdx.z;
        Bp    = Bw + (size_t)z * D_ * K3_;
        bias  = (z == 0) ? b0 : (z == 1) ? b1 : b2;
        Cp    = (z == 0) ? o0 : (z == 1) ? o1 : o2;
        scale = (z == 0) ? 0.125f : 1.0f;
    } else {
        Bp = Bw; bias = b0; Cp = o0; scale = 1.0f;
    }

    // loader: 128 rows x 32 halfs (64B = 4 chunks) for A and B each
    const int lr = tid >> 2;        // row for this thread's chunks
    const int lc = (tid & 3) << 4;  // byte col within row (0,16,32,48)
    const int gc = (tid & 3) << 3;  // half col (0,8,16,24)
    auto load_stage = [&](int i) {
        const uint32_t st = sb + (i & 3) * STG_SZ;
        const int k0 = i << 5;
#pragma unroll
        for (int h = 0; h < 2; h++) {
            int r = lr + (h << 6);
            CP16(st + r * ROW_ST + lc,           A  + (size_t)(bm + r) * K3_ + k0 + gc);
            CP16(st + A_BYTES + r * ROW_ST + lc, Bp + (size_t)(bn + r) * K3_ + k0 + gc);
        }
        CP_COMMIT();
    };

    load_stage(0); load_stage(1); load_stage(2);

    // ldmatrix lane address components
    const int a_row  = lane & 15;
    const int a_koff = ((lane >> 4) << 3);                 // halfs
    const int b_row  = (lane & 7) + ((lane >> 4) << 3);
    const int b_koff = (((lane >> 3) & 1) << 3);
    const uint32_t aAddr = sb + (wm * 64 + a_row) * ROW_ST + a_koff * 2;
    const uint32_t bAddr = sb + A_BYTES + (wn * 32 + b_row) * ROW_ST + b_koff * 2;

    float c[4][4][4];
#pragma unroll
    for (int i = 0; i < 4; i++)
#pragma unroll
        for (int j = 0; j < 4; j++)
#pragma unroll
            for (int q = 0; q < 4; q++) c[i][j][q] = 0.f;

#pragma unroll 1
    for (int i = 0; i < NITER_; i++) {
        asm volatile("cp.async.wait_group 2;" ::: "memory");
        __syncthreads();
        const uint32_t so = (i & 3) * STG_SZ;
#pragma unroll
        for (int kk = 0; kk < 2; kk++) {
            uint32_t a[4][4], b[4][2];
#pragma unroll
            for (int mt = 0; mt < 4; mt++)
                LDSM4(a[mt], aAddr + so + mt * (16 * ROW_ST) + kk * 32);
#pragma unroll
            for (int np = 0; np < 2; np++) {
                uint32_t r[4];
                LDSM4(r, bAddr + so + np * (16 * ROW_ST) + kk * 32);
                b[np * 2][0] = r[0]; b[np * 2][1] = r[1];
                b[np * 2 + 1][0] = r[2]; b[np * 2 + 1][1] = r[3];
            }
#pragma unroll
            for (int mt = 0; mt < 4; mt++)
#pragma unroll
                for (int nt = 0; nt < 4; nt++)
                    MMA16816(c[mt][nt], a[mt], b[nt]);
        }
        if (i + 3 < NITER_) load_stage(i + 3);
        else                CP_COMMIT();
    }

    // epilogue: bias + scale, direct stores (float2, coalesced in 32B groups)
    const int row0 = bm + wm * 64 + (lane >> 2);
    const int col0 = bn + wn * 32 + ((lane & 3) << 1);
#pragma unroll
    for (int mt = 0; mt < 4; mt++) {
#pragma unroll
        for (int nt = 0; nt < 4; nt++) {
            int gn = col0 + nt * 8;
            float bx = bias[gn], by = bias[gn + 1];
#pragma unroll
            for (int half = 0; half < 2; half++) {
                int gm = row0 + mt * 16 + half * 8;
                float2 o;
                o.x = (c[mt][nt][half * 2 + 0] + bx) * scale;
                o.y = (c[mt][nt][half * 2 + 1] + by) * scale;
                if (MODE == 0) {
                    *(float2*)(Cp + (size_t)gm * D_ + gn) = o;
                } else {
                    int bb = gm >> 11, ss = gm & (S_ - 1);
                    int hh = gn >> 6,  dd = gn & (DH_ - 1);
                    *(float2*)(Cp + ((((size_t)bb * H_ + hh) * S_ + ss) << 6) + dd) = o;
                }
            }
        }
    }
}

// ---------------------------------------------------------------------------
// Windowed attention — epilogue emits split layout [M,3072] = [hi | lo | hi]
// ---------------------------------------------------------------------------
#define AT_ST 68

__global__ __launch_bounds__(256) void attn_kernel(
    const float* __restrict__ Q, const float* __restrict__ K,
    const float* __restrict__ V, unsigned short* __restrict__ Osplit)
{
    extern __shared__ float sm[];
    float* Qs = sm;
    float* Ks = Qs + 64 * AT_ST;
    float* Vs = Ks + 64 * AT_ST;
    float* Ps = Vs + 64 * AT_ST;

    const int tid = threadIdx.x;
    const int q0  = blockIdx.x << 6;
    const int h   = blockIdx.y;
    const int b   = blockIdx.z;
    const size_t bh = ((size_t)b * H_ + h) * S_;

    const int rg = tid >> 4;
    const int cg = tid & 15;

    {
        const float* src = Q + (bh + q0) * DH_;
#pragma unroll
        for (int t = 0; t < 4; t++) {
            int i = tid + (t << 8);
            int row = i >> 4;
            int c4  = (i & 15) << 2;
            *(float4*)(Qs + row * AT_ST + c4) = *(const float4*)(src + (row << 6) + c4);
        }
    }

    float m[4], l[4], acc[4][4];
#pragma unroll
    for (int i = 0; i < 4; i++) {
        m[i] = -1e30f; l[i] = 0.f;
#pragma unroll
        for (int j = 0; j < 4; j++) acc[i][j] = 0.f;
    }

    const int kstart = (q0 - WIN_) > 0 ? (q0 - WIN_) : 0;
    for (int kb = kstart; kb <= q0; kb += 64) {
        __syncthreads();
        {
            const float* ksrc = K + (bh + kb) * DH_;
            const float* vsrc = V + (bh + kb) * DH_;
#pragma unroll
            for (int t = 0; t < 4; t++) {
                int i = tid + (t << 8);
                int row = i >> 4;
                int c4  = (i & 15) << 2;
                *(float4*)(Ks + row * AT_ST + c4) = *(const float4*)(ksrc + (row << 6) + c4);
                *(float4*)(Vs + row * AT_ST + c4) = *(const float4*)(vsrc + (row << 6) + c4);
            }
        }
        __syncthreads();

        float s[4][4];
#pragma unroll
        for (int i = 0; i < 4; i++)
#pragma unroll
            for (int j = 0; j < 4; j++) s[i][j] = 0.f;

#pragma unroll
        for (int kk = 0; kk < 64; kk += 4) {
            float4 qv[4], kv[4];
#pragma unroll
            for (int i = 0; i < 4; i++)
                qv[i] = *(const float4*)(Qs + (rg + 16 * i) * AT_ST + kk);
#pragma unroll
            for (int j = 0; j < 4; j++)
                kv[j] = *(const float4*)(Ks + (cg + 16 * j) * AT_ST + kk);
#pragma unroll
            for (int i = 0; i < 4; i++)
#pragma unroll
                for (int j = 0; j < 4; j++)
                    s[i][j] += qv[i].x * kv[j].x + qv[i].y * kv[j].y
                             + qv[i].z * kv[j].z + qv[i].w * kv[j].w;
        }

#pragma unroll
        for (int i = 0; i < 4; i++) {
            int qi = q0 + rg + 16 * i;
            float mx = -1e30f;
#pragma unroll
            for (int j = 0; j < 4; j++) {
                int kj = kb + cg + 16 * j;
                bool valid = (kj <= qi) && ((qi - kj) <= WIN_);
                if (!valid) s[i][j] = -1e30f;
                mx = fmaxf(mx, s[i][j]);
            }
#pragma unroll
            for (int off = 8; off >= 1; off >>= 1)
                mx = fmaxf(mx, __shfl_xor_sync(0xffffffffu, mx, off, 16));
            float mn   = fmaxf(m[i], mx);
            float corr = __expf(m[i] - mn);
            float ps = 0.f;
#pragma unroll
            for (int j = 0; j < 4; j++) {
                float p = __expf(s[i][j] - mn);
                s[i][j] = p;
                ps += p;
            }
#pragma unroll
            for (int off = 8; off >= 1; off >>= 1)
                ps += __shfl_xor_sync(0xffffffffu, ps, off, 16);
            l[i] = l[i] * corr + ps;
            m[i] = mn;
#pragma unroll
            for (int j = 0; j < 4; j++) acc[i][j] *= corr;
#pragma unroll
            for (int j = 0; j < 4; j++)
                Ps[(rg + 16 * i) * AT_ST + cg + 16 * j] = s[i][j];
        }
        __syncthreads();

#pragma unroll 4
        for (int jk = 0; jk < 64; jk++) {
            float4 vv = *(const float4*)(Vs + jk * AT_ST + (cg << 2));
            float pv[4];
#pragma unroll
            for (int i = 0; i < 4; i++)
                pv[i] = Ps[(rg + 16 * i) * AT_ST + jk];
#pragma unroll
            for (int i = 0; i < 4; i++) {
                acc[i][0] += pv[i] * vv.x;
                acc[i][1] += pv[i] * vv.y;
                acc[i][2] += pv[i] * vv.z;
                acc[i][3] += pv[i] * vv.w;
            }
        }
    }

#pragma unroll
    for (int i = 0; i < 4; i++) {
        int row = rg + 16 * i;
        float inv = 1.f / l[i];
        float vals[4] = { acc[i][0] * inv, acc[i][1] * inv,
                          acc[i][2] * inv, acc[i][3] * inv };
        ushort4 uh, ul;
        split1(vals[0], uh.x, ul.x);
        split1(vals[1], uh.y, ul.y);
        split1(vals[2], uh.z, ul.z);
        split1(vals[3], uh.w, ul.w);
        size_t base = ((size_t)b * S_ + q0 + row) * K3_ + (h << 6) + (cg << 2);
        *(ushort4*)(Osplit + base)        = uh;   // hi  (term 1)
        *(ushort4*)(Osplit + base + 1024) = ul;   // lo  (term 2)
        *(ushort4*)(Osplit + base + 2048) = uh;   // hi  (term 3)
    }
}

// ---------------------------------------------------------------------------
extern "C" void kernel_launch(void* const* d_in, const int* in_sizes, int n_in,
                              void* d_out, int out_size)
{
    const float* x  = (const float*)d_in[0];
    const float* wq = (const float*)d_in[1];
    const float* bq = (const float*)d_in[2];
    const float* wk = (const float*)d_in[3];
    const float* bk = (const float*)d_in[4];
    const float* wv = (const float*)d_in[5];
    const float* bv = (const float*)d_in[6];
    const float* wo = (const float*)d_in[7];
    const float* bo = (const float*)d_in[8];
    float* out = (float*)d_out;

    float *qp, *kp, *vp;
    unsigned short *xs, *ws, *wos, *aos;
    cudaGetSymbolAddress((void**)&qp,  g_q);
    cudaGetSymbolAddress((void**)&kp,  g_k);
    cudaGetSymbolAddress((void**)&vp,  g_v);
    cudaGetSymbolAddress((void**)&xs,  g_xs);
    cudaGetSymbolAddress((void**)&ws,  g_ws);
    cudaGetSymbolAddress((void**)&wos, g_wos);
    cudaGetSymbolAddress((void**)&aos, g_aos);

    cudaFuncSetAttribute(hgemm<0>, cudaFuncAttributeMaxDynamicSharedMemorySize, GEMM_SMEM);
    cudaFuncSetAttribute(hgemm<1>, cudaFuncAttributeMaxDynamicSharedMemorySize, GEMM_SMEM);

    // Prep: operand splits
    split_x_kernel<<<(M_ * D_) / (256 * 4), 256>>>((const float4*)x, xs);
    dim3 tg(32, 32), tb(32, 8);
    split_w_t_kernel<<<tg, tb>>>(wq, ws);
    split_w_t_kernel<<<tg, tb>>>(wk, ws + (size_t)D_ * K3_);
    split_w_t_kernel<<<tg, tb>>>(wv, ws + (size_t)2 * D_ * K3_);
    split_w_t_kernel<<<tg, tb>>>(wo, wos);

    // Fused QKV projections (z selects Q/K/V; 1/sqrt(DH) folded into Q)
    dim3 gq(D_ / 128, M_ / 128, 3);   // (8, 32, 3)
    hgemm<1><<<gq, 256, GEMM_SMEM>>>(
        (const __nv_bfloat16*)xs, (const __nv_bfloat16*)ws,
        bq, bk, bv, qp, kp, vp);

    // Attention
    const int smem_bytes = 4 * 64 * AT_ST * (int)sizeof(float);
    cudaFuncSetAttribute(attn_kernel, cudaFuncAttributeMaxDynamicSharedMemorySize, smem_bytes);
    attn_kernel<<<dim3(S_ / 64, H_, B_), 256, smem_bytes>>>(qp, kp, vp, aos);

    // Output projection
    dim3 go(D_ / 128, M_ / 128, 1);
    hgemm<0><<<go, 256, GEMM_SMEM>>>(
        (const __nv_bfloat16*)aos, (const __nv_bfloat16*)wos,
        bo, bo, bo, out, out, out);
}

// round 4
// speedup vs baseline: 2.1653x; 1.1811x over previous
#include <cuda_runtime.h>
#include <cuda_bf16.h>
#include <cuda_fp16.h>
#include <math.h>
#include <cstdint>

#define B_   2
#define S_   2048
#define D_   1024
#define H_   16
#define DH_  64
#define WIN_ 256
#define M_   (B_*S_)        // 4096
#define K3_  3072           // split-GEMM K (hi|lo|hi)

// ---------------------------------------------------------------------------
// Scratch (static device globals — no allocation)
// ---------------------------------------------------------------------------
__device__ __align__(16) float g_q [B_*H_*S_*DH_];
__device__ __align__(16) float g_k [B_*H_*S_*DH_];
__device__ __align__(16) float g_v [B_*H_*S_*DH_];
__device__ __align__(16) __nv_bfloat16 g_xs [(size_t)M_*K3_];   // x split [M,3072]
__device__ __align__(16) __nv_bfloat16 g_ws [(size_t)3*D_*K3_]; // wq|wk|wv split [N,3072]
__device__ __align__(16) __nv_bfloat16 g_wos[(size_t)D_*K3_];   // wo split
__device__ __align__(16) __nv_bfloat16 g_aos[(size_t)M_*K3_];   // attn out split

// ---------------------------------------------------------------------------
// helpers
// ---------------------------------------------------------------------------
__device__ __forceinline__ uint32_t smem_u32(const void* p) {
    uint32_t a;
    asm("{ .reg .u64 t; cvta.to.shared.u64 t, %1; cvt.u32.u64 %0, t; }"
        : "=r"(a) : "l"(p));
    return a;
}

#define CP16(sm_addr, gptr) \
    asm volatile("cp.async.cg.shared.global [%0], [%1], 16;" \
                 :: "r"(sm_addr), "l"(gptr) : "memory")
#define CP_COMMIT() asm volatile("cp.async.commit_group;" ::: "memory")

#define LDSM4(r, addr) \
    asm volatile("ldmatrix.sync.aligned.m8n8.x4.shared.b16 {%0,%1,%2,%3}, [%4];" \
        : "=r"((r)[0]), "=r"((r)[1]), "=r"((r)[2]), "=r"((r)[3]) : "r"(addr))

#define LDSM4T(r, addr) \
    asm volatile("ldmatrix.sync.aligned.m8n8.x4.trans.shared.b16 {%0,%1,%2,%3}, [%4];" \
        : "=r"((r)[0]), "=r"((r)[1]), "=r"((r)[2]), "=r"((r)[3]) : "r"(addr))

#define MMA16816(c, a, b) \
    asm volatile("mma.sync.aligned.m16n8k16.row.col.f32.bf16.bf16.f32 " \
        "{%0,%1,%2,%3}, {%4,%5,%6,%7}, {%8,%9}, {%0,%1,%2,%3};" \
        : "+f"((c)[0]), "+f"((c)[1]), "+f"((c)[2]), "+f"((c)[3]) \
        : "r"((a)[0]), "r"((a)[1]), "r"((a)[2]), "r"((a)[3]), \
          "r"((b)[0]), "r"((b)[1]))

#define MMAF16(c, a, b) \
    asm volatile("mma.sync.aligned.m16n8k16.row.col.f32.f16.f16.f32 " \
        "{%0,%1,%2,%3}, {%4,%5,%6,%7}, {%8,%9}, {%0,%1,%2,%3};" \
        : "+f"((c)[0]), "+f"((c)[1]), "+f"((c)[2]), "+f"((c)[3]) \
        : "r"((a)[0]), "r"((a)[1]), "r"((a)[2]), "r"((a)[3]), \
          "r"((b)[0]), "r"((b)[1]))

__device__ __forceinline__ void split1(float f, unsigned short& h, unsigned short& l) {
    __nv_bfloat16 hb = __float2bfloat16(f);
    float r = f - __bfloat162float(hb);
    __nv_bfloat16 lb = __float2bfloat16(r);
    h = *reinterpret_cast<unsigned short*>(&hb);
    l = *reinterpret_cast<unsigned short*>(&lb);
}

__device__ __forceinline__ uint32_t h2pack(float a, float b) {
    __half2 h = __floats2half2_rn(a, b);
    return *reinterpret_cast<uint32_t*>(&h);
}

// fp16 hi/lo split of a float4 -> packed half2 pairs
__device__ __forceinline__ void cvt4_f16(float4 f, uint32_t& h01, uint32_t& h23,
                                         uint32_t& l01, uint32_t& l23) {
    __half hx = __float2half_rn(f.x), hy = __float2half_rn(f.y);
    __half hz = __float2half_rn(f.z), hw = __float2half_rn(f.w);
    float lx = f.x - __half2float(hx), ly = f.y - __half2float(hy);
    float lz = f.z - __half2float(hz), lw = f.w - __half2float(hw);
    __half2 a = __halves2half2(hx, hy), b = __halves2half2(hz, hw);
    h01 = *reinterpret_cast<uint32_t*>(&a);
    h23 = *reinterpret_cast<uint32_t*>(&b);
    l01 = h2pack(lx, ly);
    l23 = h2pack(lz, lw);
}

// ---------------------------------------------------------------------------
// Prep: split x into [M,3072] = [hi | lo | hi]
// ---------------------------------------------------------------------------
__global__ __launch_bounds__(256) void split_x_kernel(
    const float4* __restrict__ x, unsigned short* __restrict__ out)
{
    int i = blockIdx.x * 256 + threadIdx.x;
    int r = i >> 8;
    int c = i & 255;
    float4 f = x[i];
    ushort4 h, l;
    split1(f.x, h.x, l.x);
    split1(f.y, h.y, l.y);
    split1(f.z, h.z, l.z);
    split1(f.w, h.w, l.w);
    size_t base = (size_t)r * K3_ + (c << 2);
    *(ushort4*)(out + base)        = h;
    *(ushort4*)(out + base + 1024) = l;
    *(ushort4*)(out + base + 2048) = h;
}

// ---------------------------------------------------------------------------
// Prep: transpose W [K,N] -> [N,3072] = [hi | hi | lo]
// ---------------------------------------------------------------------------
__global__ __launch_bounds__(256) void split_w_t_kernel(
    const float* __restrict__ w, unsigned short* __restrict__ out)
{
    __shared__ float t[32][33];
    int tx = threadIdx.x, ty = threadIdx.y;
    int n0 = blockIdx.x * 32, k0 = blockIdx.y * 32;
#pragma unroll
    for (int j = 0; j < 32; j += 8)
        t[ty + j][tx] = w[(size_t)(k0 + ty + j) * D_ + n0 + tx];
    __syncthreads();
#pragma unroll
    for (int j = 0; j < 32; j += 8) {
        float f = t[tx][ty + j];
        unsigned short h, l;
        split1(f, h, l);
        size_t o = (size_t)(n0 + ty + j) * K3_ + k0 + tx;
        out[o]        = h;
        out[o + 1024] = h;
        out[o + 2048] = l;
    }
}

// ---------------------------------------------------------------------------
// HMMA GEMM (unchanged from round 3): C = A'[M,3072] @ B'[N,3072]^T
// ---------------------------------------------------------------------------
#define BK_      32
#define NITER_   (K3_ / BK_)       // 96
#define ROW_ST   80
#define A_BYTES  (128 * ROW_ST)
#define STG_SZ   (2 * A_BYTES)
#define GEMM_SMEM (4 * STG_SZ)

template<int MODE>
__global__ __launch_bounds__(256) void hgemm(
    const __nv_bfloat16* __restrict__ A, const __nv_bfloat16* __restrict__ Bw,
    const float* __restrict__ b0, const float* __restrict__ b1, const float* __restrict__ b2,
    float* __restrict__ o0, float* __restrict__ o1, float* __restrict__ o2)
{
    extern __shared__ char smc[];
    const uint32_t sb = smem_u32(smc);
    const int tid  = threadIdx.x;
    const int lane = tid & 31;
    const int wid  = tid >> 5;
    const int wm   = wid >> 2;
    const int wn   = wid & 3;
    const int bm   = blockIdx.y << 7;
    const int bn   = blockIdx.x << 7;

    const __nv_bfloat16* Bp;
    const float* bias;
    float* Cp;
    float scale;
    if (MODE == 1) {
        int z = blockIdx.z;
        Bp    = Bw + (size_t)z * D_ * K3_;
        bias  = (z == 0) ? b0 : (z == 1) ? b1 : b2;
        Cp    = (z == 0) ? o0 : (z == 1) ? o1 : o2;
        scale = (z == 0) ? 0.125f : 1.0f;
    } else {
        Bp = Bw; bias = b0; Cp = o0; scale = 1.0f;
    }

    const int lr = tid >> 2;
    const int lc = (tid & 3) << 4;
    const int gc = (tid & 3) << 3;
    auto load_stage = [&](int i) {
        const uint32_t st = sb + (i & 3) * STG_SZ;
        const int k0 = i << 5;
#pragma unroll
        for (int h = 0; h < 2; h++) {
            int r = lr + (h << 6);
            CP16(st + r * ROW_ST + lc,           A  + (size_t)(bm + r) * K3_ + k0 + gc);
            CP16(st + A_BYTES + r * ROW_ST + lc, Bp + (size_t)(bn + r) * K3_ + k0 + gc);
        }
        CP_COMMIT();
    };

    load_stage(0); load_stage(1); load_stage(2);

    const int a_row  = lane & 15;
    const int a_koff = ((lane >> 4) << 3);
    const int b_row  = (lane & 7) + ((lane >> 4) << 3);
    const int b_koff = (((lane >> 3) & 1) << 3);
    const uint32_t aAddr = sb + (wm * 64 + a_row) * ROW_ST + a_koff * 2;
    const uint32_t bAddr = sb + A_BYTES + (wn * 32 + b_row) * ROW_ST + b_koff * 2;

    float c[4][4][4];
#pragma unroll
    for (int i = 0; i < 4; i++)
#pragma unroll
        for (int j = 0; j < 4; j++)
#pragma unroll
            for (int q = 0; q < 4; q++) c[i][j][q] = 0.f;

#pragma unroll 1
    for (int i = 0; i < NITER_; i++) {
        asm volatile("cp.async.wait_group 2;" ::: "memory");
        __syncthreads();
        const uint32_t so = (i & 3) * STG_SZ;
#pragma unroll
        for (int kk = 0; kk < 2; kk++) {
            uint32_t a[4][4], b[4][2];
#pragma unroll
            for (int mt = 0; mt < 4; mt++)
                LDSM4(a[mt], aAddr + so + mt * (16 * ROW_ST) + kk * 32);
#pragma unroll
            for (int np = 0; np < 2; np++) {
                uint32_t r[4];
                LDSM4(r, bAddr + so + np * (16 * ROW_ST) + kk * 32);
                b[np * 2][0] = r[0]; b[np * 2][1] = r[1];
                b[np * 2 + 1][0] = r[2]; b[np * 2 + 1][1] = r[3];
            }
#pragma unroll
            for (int mt = 0; mt < 4; mt++)
#pragma unroll
                for (int nt = 0; nt < 4; nt++)
                    MMA16816(c[mt][nt], a[mt], b[nt]);
        }
        if (i + 3 < NITER_) load_stage(i + 3);
        else                CP_COMMIT();
    }

    const int row0 = bm + wm * 64 + (lane >> 2);
    const int col0 = bn + wn * 32 + ((lane & 3) << 1);
#pragma unroll
    for (int mt = 0; mt < 4; mt++) {
#pragma unroll
        for (int nt = 0; nt < 4; nt++) {
            int gn = col0 + nt * 8;
            float bx = bias[gn], by = bias[gn + 1];
#pragma unroll
            for (int half = 0; half < 2; half++) {
                int gm = row0 + mt * 16 + half * 8;
                float2 o;
                o.x = (c[mt][nt][half * 2 + 0] + bx) * scale;
                o.y = (c[mt][nt][half * 2 + 1] + by) * scale;
                if (MODE == 0) {
                    *(float2*)(Cp + (size_t)gm * D_ + gn) = o;
                } else {
                    int bb = gm >> 11, ss = gm & (S_ - 1);
                    int hh = gn >> 6,  dd = gn & (DH_ - 1);
                    *(float2*)(Cp + ((((size_t)bb * H_ + hh) * S_ + ss) << 6) + dd) = o;
                }
            }
        }
    }
}

// ---------------------------------------------------------------------------
// HMMA windowed attention: block = (128 q-rows, head, batch), 8 warps.
// Warp = 16 q-rows x full 64-key chunk (softmax rows in-warp).
// fp16 3-term split for QK^T and PV (error ~2^-22).
// Epilogue: normalize + bf16 [hi|lo|hi] split store for O projection.
// ---------------------------------------------------------------------------
#define AROW    72                    // halfs per smem row (144B, 16B-aligned, LDSM conflict-free)
#define QT_     128
#define ATT_SMEM ((2*128 + 4*64) * AROW * 2)   // 73728 B

__global__ __launch_bounds__(256) void attn_mma(
    const float* __restrict__ Q, const float* __restrict__ K,
    const float* __restrict__ V, unsigned short* __restrict__ Osplit)
{
    extern __shared__ char sma[];
    __half* Qh = reinterpret_cast<__half*>(sma);
    __half* Ql = Qh + 128 * AROW;
    __half* Kh = Ql + 128 * AROW;
    __half* Kl = Kh + 64 * AROW;
    __half* Vh = Kl + 64 * AROW;
    __half* Vl = Vh + 64 * AROW;

    const int tid  = threadIdx.x;
    const int lane = tid & 31;
    const int w    = tid >> 5;
    const int q0t  = blockIdx.x << 7;
    const int h    = blockIdx.y;
    const int b    = blockIdx.z;
    const size_t bh = ((size_t)b * H_ + h) * S_;

    // ---- stage Q tile (128x64) as fp16 hi/lo ----
    {
        const float* Qg = Q + (bh + q0t) * DH_;
#pragma unroll
        for (int it = 0; it < 8; it++) {
            int idx = it * 256 + tid;
            int row = idx >> 4, c4 = (idx & 15) << 2;
            float4 f = *(const float4*)(Qg + (row << 6) + c4);
            uint32_t h01, h23, l01, l23;
            cvt4_f16(f, h01, h23, l01, l23);
            uint32_t* dh = reinterpret_cast<uint32_t*>(Qh + row * AROW + c4);
            uint32_t* dl = reinterpret_cast<uint32_t*>(Ql + row * AROW + c4);
            dh[0] = h01; dh[1] = h23;
            dl[0] = l01; dl[1] = l23;
        }
    }

    // smem base addrs for ldmatrix
    const uint32_t sQh = smem_u32(Qh), sQl = smem_u32(Ql);
    const uint32_t sKh = smem_u32(Kh), sKl = smem_u32(Kl);
    const uint32_t sVh = smem_u32(Vh), sVl = smem_u32(Vl);

    // A (Q): lanes 0-15 rows, lanes 16-31 k+8
    const uint32_t aOff = (w * 16 + (lane & 15)) * (AROW * 2) + ((lane >> 4) << 4);
    // B (K, [n=key][k=dh], non-trans): rows n
    const uint32_t bKOff = ((lane & 7) + ((lane >> 4) << 3)) * (AROW * 2)
                         + (((lane >> 3) & 1) << 4);
    // B (V, [k=key][n=d], trans): rows k
    const uint32_t bVOff = ((lane & 7) + (((lane >> 3) & 1) << 3)) * (AROW * 2)
                         + ((lane >> 4) << 4);

    float m2[2] = {-1e30f, -1e30f};
    float l2[2] = {0.f, 0.f};
    float co[8][4];
#pragma unroll
    for (int i = 0; i < 8; i++)
#pragma unroll
        for (int j = 0; j < 4; j++) co[i][j] = 0.f;

    const int baserow = q0t + w * 16 + (lane >> 2);
    const int jc0     = (lane & 3) << 1;

    const int kstart = (q0t - WIN_) > 0 ? (q0t - WIN_) : 0;
    const int kend   = q0t + 64;

    for (int kb = kstart; kb <= kend; kb += 64) {
        __syncthreads();
        // ---- stage K,V chunk (64x64 each) as fp16 hi/lo ----
        {
            const float* Kg = K + (bh + kb) * DH_;
            const float* Vg = V + (bh + kb) * DH_;
#pragma unroll
            for (int it = 0; it < 4; it++) {
                int idx = it * 256 + tid;
                int row = idx >> 4, c4 = (idx & 15) << 2;
                uint32_t h01, h23, l01, l23;
                float4 fk = *(const float4*)(Kg + (row << 6) + c4);
                cvt4_f16(fk, h01, h23, l01, l23);
                uint32_t* dh = reinterpret_cast<uint32_t*>(Kh + row * AROW + c4);
                uint32_t* dl = reinterpret_cast<uint32_t*>(Kl + row * AROW + c4);
                dh[0] = h01; dh[1] = h23; dl[0] = l01; dl[1] = l23;
                float4 fv = *(const float4*)(Vg + (row << 6) + c4);
                cvt4_f16(fv, h01, h23, l01, l23);
                dh = reinterpret_cast<uint32_t*>(Vh + row * AROW + c4);
                dl = reinterpret_cast<uint32_t*>(Vl + row * AROW + c4);
                dh[0] = h01; dh[1] = h23; dl[0] = l01; dl[1] = l23;
            }
        }
        __syncthreads();

        // ---- scores: s[nt] = Qh*Kh + Ql*Kh + Qh*Kl  (16q x 64keys per warp) ----
        float s[8][4];
#pragma unroll
        for (int i = 0; i < 8; i++)
#pragma unroll
            for (int j = 0; j < 4; j++) s[i][j] = 0.f;

#pragma unroll
        for (int ks = 0; ks < 4; ks++) {
            uint32_t aH[4], aL[4];
            LDSM4(aH, sQh + aOff + ks * 32);
            LDSM4(aL, sQl + aOff + ks * 32);
#pragma unroll
            for (int np = 0; np < 4; np++) {
                uint32_t bH[4], bL[4];
                LDSM4(bH, sKh + bKOff + np * (16 * AROW * 2) + ks * 32);
                LDSM4(bL, sKl + bKOff + np * (16 * AROW * 2) + ks * 32);
                MMAF16(s[np * 2],     aH, bH);
                MMAF16(s[np * 2],     aL, bH);
                MMAF16(s[np * 2],     aH, bL);
                MMAF16(s[np * 2 + 1], aH, bH + 2);
                MMAF16(s[np * 2 + 1], aL, bH + 2);
                MMAF16(s[np * 2 + 1], aH, bL + 2);
            }
        }

        // ---- mask + online softmax (per row-half) ----
#pragma unroll
        for (int rh = 0; rh < 2; rh++) {
            int qi = baserow + rh * 8;
            float mx = -1e30f;
#pragma unroll
            for (int nt = 0; nt < 8; nt++) {
#pragma unroll
                for (int j = 0; j < 2; j++) {
                    int kj = kb + nt * 8 + jc0 + j;
                    float& v = s[nt][rh * 2 + j];
                    if (kj > qi || (qi - kj) > WIN_) v = -1e30f;
                    mx = fmaxf(mx, v);
                }
            }
            mx = fmaxf(mx, __shfl_xor_sync(0xffffffffu, mx, 1));
            mx = fmaxf(mx, __shfl_xor_sync(0xffffffffu, mx, 2));
            float mn   = fmaxf(m2[rh], mx);
            float corr = __expf(m2[rh] - mn);
            m2[rh] = mn;
            float ps = 0.f;
#pragma unroll
            for (int nt = 0; nt < 8; nt++) {
#pragma unroll
                for (int j = 0; j < 2; j++) {
                    float p = __expf(s[nt][rh * 2 + j] - mn);
                    s[nt][rh * 2 + j] = p;
                    ps += p;
                }
            }
            ps += __shfl_xor_sync(0xffffffffu, ps, 1);
            ps += __shfl_xor_sync(0xffffffffu, ps, 2);
            l2[rh] = l2[rh] * corr + ps;
#pragma unroll
            for (int nt = 0; nt < 8; nt++) {
                co[nt][rh * 2]     *= corr;
                co[nt][rh * 2 + 1] *= corr;
            }
        }

        // ---- convert P to fp16 hi/lo A-frags (register repack) ----
        uint32_t ph[8][2], pl[8][2];
#pragma unroll
        for (int nt = 0; nt < 8; nt++) {
            __half h0 = __float2half_rn(s[nt][0]), h1 = __float2half_rn(s[nt][1]);
            __half h2 = __float2half_rn(s[nt][2]), h3 = __float2half_rn(s[nt][3]);
            __half2 p01 = __halves2half2(h0, h1), p23 = __halves2half2(h2, h3);
            ph[nt][0] = *reinterpret_cast<uint32_t*>(&p01);
            ph[nt][1] = *reinterpret_cast<uint32_t*>(&p23);
            pl[nt][0] = h2pack(s[nt][0] - __half2float(h0), s[nt][1] - __half2float(h1));
            pl[nt][1] = h2pack(s[nt][2] - __half2float(h2), s[nt][3] - __half2float(h3));
        }

        // ---- PV: co += Ph*Vh + Pl*Vh + Ph*Vl ----
#pragma unroll
        for (int ks = 0; ks < 4; ks++) {
            uint32_t aPh[4] = { ph[2*ks][0], ph[2*ks][1], ph[2*ks+1][0], ph[2*ks+1][1] };
            uint32_t aPl[4] = { pl[2*ks][0], pl[2*ks][1], pl[2*ks+1][0], pl[2*ks+1][1] };
#pragma unroll
            for (int np = 0; np < 4; np++) {
                uint32_t vH[4], vL[4];
                LDSM4T(vH, sVh + bVOff + ks * (16 * AROW * 2) + np * 32);
                LDSM4T(vL, sVl + bVOff + ks * (16 * AROW * 2) + np * 32);
                MMAF16(co[np * 2],     aPh, vH);
                MMAF16(co[np * 2],     aPl, vH);
                MMAF16(co[np * 2],     aPh, vL);
                MMAF16(co[np * 2 + 1], aPh, vH + 2);
                MMAF16(co[np * 2 + 1], aPl, vH + 2);
                MMAF16(co[np * 2 + 1], aPh, vL + 2);
            }
        }
    }

    // ---- normalize + bf16 [hi|lo|hi] split store ----
    const int ocol0 = (h << 6) + jc0;
#pragma unroll
    for (int rh = 0; rh < 2; rh++) {
        float inv = 1.f / l2[rh];
        size_t rbase = (size_t)(b * S_ + baserow - q0t + q0t + rh * 8) * K3_;  // (global row)*K3
#pragma unroll
        for (int nt = 0; nt < 8; nt++) {
            float v0 = co[nt][rh * 2]     * inv;
            float v1 = co[nt][rh * 2 + 1] * inv;
            unsigned short h0, l0, h1, l1;
            split1(v0, h0, l0);
            split1(v1, h1, l1);
            uint32_t hp = ((uint32_t)h1 << 16) | h0;
            uint32_t lp = ((uint32_t)l1 << 16) | l0;
            size_t p = rbase + ocol0 + nt * 8;
            *(uint32_t*)(Osplit + p)        = hp;
            *(uint32_t*)(Osplit + p + 1024) = lp;
            *(uint32_t*)(Osplit + p + 2048) = hp;
        }
    }
}

// ---------------------------------------------------------------------------
extern "C" void kernel_launch(void* const* d_in, const int* in_sizes, int n_in,
                              void* d_out, int out_size)
{
    const float* x  = (const float*)d_in[0];
    const float* wq = (const float*)d_in[1];
    const float* bq = (const float*)d_in[2];
    const float* wk = (const float*)d_in[3];
    const float* bk = (const float*)d_in[4];
    const float* wv = (const float*)d_in[5];
    const float* bv = (const float*)d_in[6];
    const float* wo = (const float*)d_in[7];
    const float* bo = (const float*)d_in[8];
    float* out = (float*)d_out;

    float *qp, *kp, *vp;
    unsigned short *xs, *ws, *wos, *aos;
    cudaGetSymbolAddress((void**)&qp,  g_q);
    cudaGetSymbolAddress((void**)&kp,  g_k);
    cudaGetSymbolAddress((void**)&vp,  g_v);
    cudaGetSymbolAddress((void**)&xs,  g_xs);
    cudaGetSymbolAddress((void**)&ws,  g_ws);
    cudaGetSymbolAddress((void**)&wos, g_wos);
    cudaGetSymbolAddress((void**)&aos, g_aos);

    cudaFuncSetAttribute(hgemm<0>, cudaFuncAttributeMaxDynamicSharedMemorySize, GEMM_SMEM);
    cudaFuncSetAttribute(hgemm<1>, cudaFuncAttributeMaxDynamicSharedMemorySize, GEMM_SMEM);
    cudaFuncSetAttribute(attn_mma, cudaFuncAttributeMaxDynamicSharedMemorySize, ATT_SMEM);

    // Prep: operand splits
    split_x_kernel<<<(M_ * D_) / (256 * 4), 256>>>((const float4*)x, xs);
    dim3 tg(32, 32), tb(32, 8);
    split_w_t_kernel<<<tg, tb>>>(wq, ws);
    split_w_t_kernel<<<tg, tb>>>(wk, ws + (size_t)D_ * K3_);
    split_w_t_kernel<<<tg, tb>>>(wv, ws + (size_t)2 * D_ * K3_);
    split_w_t_kernel<<<tg, tb>>>(wo, wos);

    // Fused QKV projections (z selects Q/K/V; 1/sqrt(DH) folded into Q)
    dim3 gq(D_ / 128, M_ / 128, 3);
    hgemm<1><<<gq, 256, GEMM_SMEM>>>(
        (const __nv_bfloat16*)xs, (const __nv_bfloat16*)ws,
        bq, bk, bv, qp, kp, vp);

    // Attention (HMMA)
    attn_mma<<<dim3(S_ / QT_, H_, B_), 256, ATT_SMEM>>>(qp, kp, vp, aos);

    // Output projection
    dim3 go(D_ / 128, M_ / 128, 1);
    hgemm<0><<<go, 256, GEMM_SMEM>>>(
        (const __nv_bfloat16*)aos, (const __nv_bfloat16*)wos,
        bo, bo, bo, out, out, out);
}

// round 5
// speedup vs baseline: 2.9219x; 1.3494x over previous
#include <cuda_runtime.h>
#include <cuda_bf16.h>
#include <cuda_fp16.h>
#include <math.h>
#include <cstdint>

#define B_   2
#define S_   2048
#define D_   1024
#define H_   16
#define DH_  64
#define WIN_ 256
#define M_   (B_*S_)        // 4096
#define K2_  2048           // split-GEMM K (hi | 64*lo)

// ---------------------------------------------------------------------------
// Scratch (static device globals — no allocation)
// ---------------------------------------------------------------------------
__device__ __align__(16) float g_q [B_*H_*S_*DH_];
__device__ __align__(16) float g_k [B_*H_*S_*DH_];
__device__ __align__(16) float g_v [B_*H_*S_*DH_];
__device__ __align__(16) __half g_xs [(size_t)M_*K2_];   // x split [M,2048] = [hi | 64*lo]
__device__ __align__(16) __half g_ws [(size_t)3*D_*K2_]; // wq|wk|wv split [N,2048] = [64*hi | hi]
__device__ __align__(16) __half g_wos[(size_t)D_*K2_];   // wo split
__device__ __align__(16) __half g_aos[(size_t)M_*K2_];   // attn out split

// ---------------------------------------------------------------------------
// helpers
// ---------------------------------------------------------------------------
__device__ __forceinline__ uint32_t smem_u32(const void* p) {
    uint32_t a;
    asm("{ .reg .u64 t; cvta.to.shared.u64 t, %1; cvt.u32.u64 %0, t; }"
        : "=r"(a) : "l"(p));
    return a;
}

#define CP16(sm_addr, gptr) \
    asm volatile("cp.async.cg.shared.global [%0], [%1], 16;" \
                 :: "r"(sm_addr), "l"(gptr) : "memory")
#define CP_COMMIT() asm volatile("cp.async.commit_group;" ::: "memory")

#define LDSM4(r, addr) \
    asm volatile("ldmatrix.sync.aligned.m8n8.x4.shared.b16 {%0,%1,%2,%3}, [%4];" \
        : "=r"((r)[0]), "=r"((r)[1]), "=r"((r)[2]), "=r"((r)[3]) : "r"(addr))

#define LDSM4T(r, addr) \
    asm volatile("ldmatrix.sync.aligned.m8n8.x4.trans.shared.b16 {%0,%1,%2,%3}, [%4];" \
        : "=r"((r)[0]), "=r"((r)[1]), "=r"((r)[2]), "=r"((r)[3]) : "r"(addr))

#define MMAF16(c, a, b) \
    asm volatile("mma.sync.aligned.m16n8k16.row.col.f32.f16.f16.f32 " \
        "{%0,%1,%2,%3}, {%4,%5,%6,%7}, {%8,%9}, {%0,%1,%2,%3};" \
        : "+f"((c)[0]), "+f"((c)[1]), "+f"((c)[2]), "+f"((c)[3]) \
        : "r"((a)[0]), "r"((a)[1]), "r"((a)[2]), "r"((a)[3]), \
          "r"((b)[0]), "r"((b)[1]))

__device__ __forceinline__ uint32_t h2pack(float a, float b) {
    __half2 h = __floats2half2_rn(a, b);
    return *reinterpret_cast<uint32_t*>(&h);
}

// fp16 split: value -> (hi, 64*lo)
__device__ __forceinline__ void split16(float f, unsigned short& h, unsigned short& l) {
    __half hb = __float2half_rn(f);
    float r = (f - __half2float(hb)) * 64.0f;
    __half lb = __float2half_rn(r);
    h = *reinterpret_cast<unsigned short*>(&hb);
    l = *reinterpret_cast<unsigned short*>(&lb);
}

// fp16 hi/lo split of a float4 -> packed half2 pairs (for attention staging)
__device__ __forceinline__ void cvt4_f16(float4 f, uint32_t& h01, uint32_t& h23,
                                         uint32_t& l01, uint32_t& l23) {
    __half hx = __float2half_rn(f.x), hy = __float2half_rn(f.y);
    __half hz = __float2half_rn(f.z), hw = __float2half_rn(f.w);
    float lx = f.x - __half2float(hx), ly = f.y - __half2float(hy);
    float lz = f.z - __half2float(hz), lw = f.w - __half2float(hw);
    __half2 a = __halves2half2(hx, hy), b = __halves2half2(hz, hw);
    h01 = *reinterpret_cast<uint32_t*>(&a);
    h23 = *reinterpret_cast<uint32_t*>(&b);
    l01 = h2pack(lx, ly);
    l23 = h2pack(lz, lw);
}

// ---------------------------------------------------------------------------
// Prep: split x into [M,2048] = [hi | 64*lo]
// ---------------------------------------------------------------------------
__global__ __launch_bounds__(256) void split_x_kernel(
    const float4* __restrict__ x, unsigned short* __restrict__ out)
{
    int i = blockIdx.x * 256 + threadIdx.x;
    int r = i >> 8;
    int c = i & 255;
    float4 f = x[i];
    ushort4 h, l;
    split16(f.x, h.x, l.x);
    split16(f.y, h.y, l.y);
    split16(f.z, h.z, l.z);
    split16(f.w, h.w, l.w);
    size_t base = (size_t)r * K2_ + (c << 2);
    *(ushort4*)(out + base)        = h;
    *(ushort4*)(out + base + 1024) = l;
}

// ---------------------------------------------------------------------------
// Prep: transpose W [K,N] -> [N,2048] = [64*hi | hi]
// ---------------------------------------------------------------------------
__global__ __launch_bounds__(256) void split_w_t_kernel(
    const float* __restrict__ w, unsigned short* __restrict__ out)
{
    __shared__ float t[32][33];
    int tx = threadIdx.x, ty = threadIdx.y;
    int n0 = blockIdx.x * 32, k0 = blockIdx.y * 32;
#pragma unroll
    for (int j = 0; j < 32; j += 8)
        t[ty + j][tx] = w[(size_t)(k0 + ty + j) * D_ + n0 + tx];
    __syncthreads();
#pragma unroll
    for (int j = 0; j < 32; j += 8) {
        float f = t[tx][ty + j];
        __half h64 = __float2half_rn(f * 64.0f);
        __half h1  = __float2half_rn(f);
        size_t o = (size_t)(n0 + ty + j) * K2_ + k0 + tx;
        out[o]        = *reinterpret_cast<unsigned short*>(&h64);
        out[o + 1024] = *reinterpret_cast<unsigned short*>(&h1);
    }
}

// ---------------------------------------------------------------------------
// HMMA GEMM: C = A'[M,2048] @ B'[N,2048]^T = 64 * (A @ Bh^T)
// 128x128 CTA tile, BK=32, 4-stage cp.async pipeline, 8 warps (2x4), 64x32/warp.
// Epilogue: o = C * (scale/64) + bias * scale.
// MODE 1: fused QKV (blockIdx.z), [B,H,S,DH] store. MODE 0: row-major store.
// ---------------------------------------------------------------------------
#define BK_      32
#define NITER_   (K2_ / BK_)       // 64
#define ROW_ST   80
#define A_BYTES  (128 * ROW_ST)
#define STG_SZ   (2 * A_BYTES)
#define GEMM_SMEM (4 * STG_SZ)

template<int MODE>
__global__ __launch_bounds__(256) void hgemm(
    const __half* __restrict__ A, const __half* __restrict__ Bw,
    const float* __restrict__ b0, const float* __restrict__ b1, const float* __restrict__ b2,
    float* __restrict__ o0, float* __restrict__ o1, float* __restrict__ o2)
{
    extern __shared__ char smc[];
    const uint32_t sb = smem_u32(smc);
    const int tid  = threadIdx.x;
    const int lane = tid & 31;
    const int wid  = tid >> 5;
    const int wm   = wid >> 2;
    const int wn   = wid & 3;
    const int bm   = blockIdx.y << 7;
    const int bn   = blockIdx.x << 7;

    const __half* Bp;
    const float* bias;
    float* Cp;
    float scale;
    if (MODE == 1) {
        int z = blockIdx.z;
        Bp    = Bw + (size_t)z * D_ * K2_;
        bias  = (z == 0) ? b0 : (z == 1) ? b1 : b2;
        Cp    = (z == 0) ? o0 : (z == 1) ? o1 : o2;
        scale = (z == 0) ? 0.125f : 1.0f;
    } else {
        Bp = Bw; bias = b0; Cp = o0; scale = 1.0f;
    }
    const float cscale = scale * 0.015625f;   // scale/64

    const int lr = tid >> 2;
    const int lc = (tid & 3) << 4;
    const int gc = (tid & 3) << 3;
    auto load_stage = [&](int i) {
        const uint32_t st = sb + (i & 3) * STG_SZ;
        const int k0 = i << 5;
#pragma unroll
        for (int h = 0; h < 2; h++) {
            int r = lr + (h << 6);
            CP16(st + r * ROW_ST + lc,           A  + (size_t)(bm + r) * K2_ + k0 + gc);
            CP16(st + A_BYTES + r * ROW_ST + lc, Bp + (size_t)(bn + r) * K2_ + k0 + gc);
        }
        CP_COMMIT();
    };

    load_stage(0); load_stage(1); load_stage(2);

    const int a_row  = lane & 15;
    const int a_koff = ((lane >> 4) << 3);
    const int b_row  = (lane & 7) + ((lane >> 4) << 3);
    const int b_koff = (((lane >> 3) & 1) << 3);
    const uint32_t aAddr = sb + (wm * 64 + a_row) * ROW_ST + a_koff * 2;
    const uint32_t bAddr = sb + A_BYTES + (wn * 32 + b_row) * ROW_ST + b_koff * 2;

    float c[4][4][4];
#pragma unroll
    for (int i = 0; i < 4; i++)
#pragma unroll
        for (int j = 0; j < 4; j++)
#pragma unroll
            for (int q = 0; q < 4; q++) c[i][j][q] = 0.f;

#pragma unroll 1
    for (int i = 0; i < NITER_; i++) {
        asm volatile("cp.async.wait_group 2;" ::: "memory");
        __syncthreads();
        const uint32_t so = (i & 3) * STG_SZ;
#pragma unroll
        for (int kk = 0; kk < 2; kk++) {
            uint32_t a[4][4], b[4][2];
#pragma unroll
            for (int mt = 0; mt < 4; mt++)
                LDSM4(a[mt], aAddr + so + mt * (16 * ROW_ST) + kk * 32);
#pragma unroll
            for (int np = 0; np < 2; np++) {
                uint32_t r[4];
                LDSM4(r, bAddr + so + np * (16 * ROW_ST) + kk * 32);
                b[np * 2][0] = r[0]; b[np * 2][1] = r[1];
                b[np * 2 + 1][0] = r[2]; b[np * 2 + 1][1] = r[3];
            }
#pragma unroll
            for (int mt = 0; mt < 4; mt++)
#pragma unroll
                for (int nt = 0; nt < 4; nt++)
                    MMAF16(c[mt][nt], a[mt], b[nt]);
        }
        if (i + 3 < NITER_) load_stage(i + 3);
        else                CP_COMMIT();
    }

    const int row0 = bm + wm * 64 + (lane >> 2);
    const int col0 = bn + wn * 32 + ((lane & 3) << 1);
#pragma unroll
    for (int mt = 0; mt < 4; mt++) {
#pragma unroll
        for (int nt = 0; nt < 4; nt++) {
            int gn = col0 + nt * 8;
            float bx = bias[gn] * scale, by = bias[gn + 1] * scale;
#pragma unroll
            for (int half = 0; half < 2; half++) {
                int gm = row0 + mt * 16 + half * 8;
                float2 o;
                o.x = c[mt][nt][half * 2 + 0] * cscale + bx;
                o.y = c[mt][nt][half * 2 + 1] * cscale + by;
                if (MODE == 0) {
                    *(float2*)(Cp + (size_t)gm * D_ + gn) = o;
                } else {
                    int bb = gm >> 11, ss = gm & (S_ - 1);
                    int hh = gn >> 6,  dd = gn & (DH_ - 1);
                    *(float2*)(Cp + ((((size_t)bb * H_ + hh) * S_ + ss) << 6) + dd) = o;
                }
            }
        }
    }
}

// ---------------------------------------------------------------------------
// HMMA windowed attention: block = (128 q-rows, head, batch), 8 warps.
// Warp = 16 q-rows x full 64-key chunk. fp16 3-term split (error ~2^-22).
// Epilogue: normalize + fp16 [hi | 64*lo] split store for O projection.
// ---------------------------------------------------------------------------
#define AROW    72
#define QT_     128
#define ATT_SMEM ((2*128 + 4*64) * AROW * 2)   // 73728 B

__global__ __launch_bounds__(256) void attn_mma(
    const float* __restrict__ Q, const float* __restrict__ K,
    const float* __restrict__ V, unsigned short* __restrict__ Osplit)
{
    extern __shared__ char sma[];
    __half* Qh = reinterpret_cast<__half*>(sma);
    __half* Ql = Qh + 128 * AROW;
    __half* Kh = Ql + 128 * AROW;
    __half* Kl = Kh + 64 * AROW;
    __half* Vh = Kl + 64 * AROW;
    __half* Vl = Vh + 64 * AROW;

    const int tid  = threadIdx.x;
    const int lane = tid & 31;
    const int w    = tid >> 5;
    const int q0t  = blockIdx.x << 7;
    const int h    = blockIdx.y;
    const int b    = blockIdx.z;
    const size_t bh = ((size_t)b * H_ + h) * S_;

    // ---- stage Q tile (128x64) as fp16 hi/lo ----
    {
        const float* Qg = Q + (bh + q0t) * DH_;
#pragma unroll
        for (int it = 0; it < 8; it++) {
            int idx = it * 256 + tid;
            int row = idx >> 4, c4 = (idx & 15) << 2;
            float4 f = *(const float4*)(Qg + (row << 6) + c4);
            uint32_t h01, h23, l01, l23;
            cvt4_f16(f, h01, h23, l01, l23);
            uint32_t* dh = reinterpret_cast<uint32_t*>(Qh + row * AROW + c4);
            uint32_t* dl = reinterpret_cast<uint32_t*>(Ql + row * AROW + c4);
            dh[0] = h01; dh[1] = h23;
            dl[0] = l01; dl[1] = l23;
        }
    }

    const uint32_t sQh = smem_u32(Qh), sQl = smem_u32(Ql);
    const uint32_t sKh = smem_u32(Kh), sKl = smem_u32(Kl);
    const uint32_t sVh = smem_u32(Vh), sVl = smem_u32(Vl);

    const uint32_t aOff = (w * 16 + (lane & 15)) * (AROW * 2) + ((lane >> 4) << 4);
    const uint32_t bKOff = ((lane & 7) + ((lane >> 4) << 3)) * (AROW * 2)
                         + (((lane >> 3) & 1) << 4);
    const uint32_t bVOff = ((lane & 7) + (((lane >> 3) & 1) << 3)) * (AROW * 2)
                         + ((lane >> 4) << 4);

    float m2[2] = {-1e30f, -1e30f};
    float l2[2] = {0.f, 0.f};
    float co[8][4];
#pragma unroll
    for (int i = 0; i < 8; i++)
#pragma unroll
        for (int j = 0; j < 4; j++) co[i][j] = 0.f;

    const int baserow = q0t + w * 16 + (lane >> 2);
    const int jc0     = (lane & 3) << 1;

    const int kstart = (q0t - WIN_) > 0 ? (q0t - WIN_) : 0;
    const int kend   = q0t + 64;

    for (int kb = kstart; kb <= kend; kb += 64) {
        __syncthreads();
        {
            const float* Kg = K + (bh + kb) * DH_;
            const float* Vg = V + (bh + kb) * DH_;
#pragma unroll
            for (int it = 0; it < 4; it++) {
                int idx = it * 256 + tid;
                int row = idx >> 4, c4 = (idx & 15) << 2;
                uint32_t h01, h23, l01, l23;
                float4 fk = *(const float4*)(Kg + (row << 6) + c4);
                cvt4_f16(fk, h01, h23, l01, l23);
                uint32_t* dh = reinterpret_cast<uint32_t*>(Kh + row * AROW + c4);
                uint32_t* dl = reinterpret_cast<uint32_t*>(Kl + row * AROW + c4);
                dh[0] = h01; dh[1] = h23; dl[0] = l01; dl[1] = l23;
                float4 fv = *(const float4*)(Vg + (row << 6) + c4);
                cvt4_f16(fv, h01, h23, l01, l23);
                dh = reinterpret_cast<uint32_t*>(Vh + row * AROW + c4);
                dl = reinterpret_cast<uint32_t*>(Vl + row * AROW + c4);
                dh[0] = h01; dh[1] = h23; dl[0] = l01; dl[1] = l23;
            }
        }
        __syncthreads();

        float s[8][4];
#pragma unroll
        for (int i = 0; i < 8; i++)
#pragma unroll
            for (int j = 0; j < 4; j++) s[i][j] = 0.f;

#pragma unroll
        for (int ks = 0; ks < 4; ks++) {
            uint32_t aH[4], aL[4];
            LDSM4(aH, sQh + aOff + ks * 32);
            LDSM4(aL, sQl + aOff + ks * 32);
#pragma unroll
            for (int np = 0; np < 4; np++) {
                uint32_t bH[4], bL[4];
                LDSM4(bH, sKh + bKOff + np * (16 * AROW * 2) + ks * 32);
                LDSM4(bL, sKl + bKOff + np * (16 * AROW * 2) + ks * 32);
                MMAF16(s[np * 2],     aH, bH);
                MMAF16(s[np * 2],     aL, bH);
                MMAF16(s[np * 2],     aH, bL);
                MMAF16(s[np * 2 + 1], aH, bH + 2);
                MMAF16(s[np * 2 + 1], aL, bH + 2);
                MMAF16(s[np * 2 + 1], aH, bL + 2);
            }
        }

#pragma unroll
        for (int rh = 0; rh < 2; rh++) {
            int qi = baserow + rh * 8;
            float mx = -1e30f;
#pragma unroll
            for (int nt = 0; nt < 8; nt++) {
#pragma unroll
                for (int j = 0; j < 2; j++) {
                    int kj = kb + nt * 8 + jc0 + j;
                    float& v = s[nt][rh * 2 + j];
                    if (kj > qi || (qi - kj) > WIN_) v = -1e30f;
                    mx = fmaxf(mx, v);
                }
            }
            mx = fmaxf(mx, __shfl_xor_sync(0xffffffffu, mx, 1));
            mx = fmaxf(mx, __shfl_xor_sync(0xffffffffu, mx, 2));
            float mn   = fmaxf(m2[rh], mx);
            float corr = __expf(m2[rh] - mn);
            m2[rh] = mn;
            float ps = 0.f;
#pragma unroll
            for (int nt = 0; nt < 8; nt++) {
#pragma unroll
                for (int j = 0; j < 2; j++) {
                    float p = __expf(s[nt][rh * 2 + j] - mn);
                    s[nt][rh * 2 + j] = p;
                    ps += p;
                }
            }
            ps += __shfl_xor_sync(0xffffffffu, ps, 1);
            ps += __shfl_xor_sync(0xffffffffu, ps, 2);
            l2[rh] = l2[rh] * corr + ps;
#pragma unroll
            for (int nt = 0; nt < 8; nt++) {
                co[nt][rh * 2]     *= corr;
                co[nt][rh * 2 + 1] *= corr;
            }
        }

        uint32_t ph[8][2], pl[8][2];
#pragma unroll
        for (int nt = 0; nt < 8; nt++) {
            __half h0 = __float2half_rn(s[nt][0]), h1 = __float2half_rn(s[nt][1]);
            __half h2 = __float2half_rn(s[nt][2]), h3 = __float2half_rn(s[nt][3]);
            __half2 p01 = __halves2half2(h0, h1), p23 = __halves2half2(h2, h3);
            ph[nt][0] = *reinterpret_cast<uint32_t*>(&p01);
            ph[nt][1] = *reinterpret_cast<uint32_t*>(&p23);
            pl[nt][0] = h2pack(s[nt][0] - __half2float(h0), s[nt][1] - __half2float(h1));
            pl[nt][1] = h2pack(s[nt][2] - __half2float(h2), s[nt][3] - __half2float(h3));
        }

#pragma unroll
        for (int ks = 0; ks < 4; ks++) {
            uint32_t aPh[4] = { ph[2*ks][0], ph[2*ks][1], ph[2*ks+1][0], ph[2*ks+1][1] };
            uint32_t aPl[4] = { pl[2*ks][0], pl[2*ks][1], pl[2*ks+1][0], pl[2*ks+1][1] };
#pragma unroll
            for (int np = 0; np < 4; np++) {
                uint32_t vH[4], vL[4];
                LDSM4T(vH, sVh + bVOff + ks * (16 * AROW * 2) + np * 32);
                LDSM4T(vL, sVl + bVOff + ks * (16 * AROW * 2) + np * 32);
                MMAF16(co[np * 2],     aPh, vH);
                MMAF16(co[np * 2],     aPl, vH);
                MMAF16(co[np * 2],     aPh, vL);
                MMAF16(co[np * 2 + 1], aPh, vH + 2);
                MMAF16(co[np * 2 + 1], aPl, vH + 2);
                MMAF16(co[np * 2 + 1], aPh, vL + 2);
            }
        }
    }

    // ---- normalize + fp16 [hi | 64*lo] split store ----
    const int ocol0 = (h << 6) + jc0;
#pragma unroll
    for (int rh = 0; rh < 2; rh++) {
        float inv = 1.f / l2[rh];
        size_t rbase = (size_t)(b * S_ + baserow + rh * 8) * K2_;
#pragma unroll
        for (int nt = 0; nt < 8; nt++) {
            float v0 = co[nt][rh * 2]     * inv;
            float v1 = co[nt][rh * 2 + 1] * inv;
            unsigned short h0, l0, h1, l1;
            split16(v0, h0, l0);
            split16(v1, h1, l1);
            uint32_t hp = ((uint32_t)h1 << 16) | h0;
            uint32_t lp = ((uint32_t)l1 << 16) | l0;
            size_t p = rbase + ocol0 + nt * 8;
            *(uint32_t*)(Osplit + p)        = hp;
            *(uint32_t*)(Osplit + p + 1024) = lp;
        }
    }
}

// ---------------------------------------------------------------------------
extern "C" void kernel_launch(void* const* d_in, const int* in_sizes, int n_in,
                              void* d_out, int out_size)
{
    const float* x  = (const float*)d_in[0];
    const float* wq = (const float*)d_in[1];
    const float* bq = (const float*)d_in[2];
    const float* wk = (const float*)d_in[3];
    const float* bk = (const float*)d_in[4];
    const float* wv = (const float*)d_in[5];
    const float* bv = (const float*)d_in[6];
    const float* wo = (const float*)d_in[7];
    const float* bo = (const float*)d_in[8];
    float* out = (float*)d_out;

    float *qp, *kp, *vp;
    unsigned short *xs, *ws, *wos, *aos;
    cudaGetSymbolAddress((void**)&qp,  g_q);
    cudaGetSymbolAddress((void**)&kp,  g_k);
    cudaGetSymbolAddress((void**)&vp,  g_v);
    cudaGetSymbolAddress((void**)&xs,  g_xs);
    cudaGetSymbolAddress((void**)&ws,  g_ws);
    cudaGetSymbolAddress((void**)&wos, g_wos);
    cudaGetSymbolAddress((void**)&aos, g_aos);

    cudaFuncSetAttribute(hgemm<0>, cudaFuncAttributeMaxDynamicSharedMemorySize, GEMM_SMEM);
    cudaFuncSetAttribute(hgemm<1>, cudaFuncAttributeMaxDynamicSharedMemorySize, GEMM_SMEM);
    cudaFuncSetAttribute(attn_mma, cudaFuncAttributeMaxDynamicSharedMemorySize, ATT_SMEM);

    // Prep: operand splits
    split_x_kernel<<<(M_ * D_) / (256 * 4), 256>>>((const float4*)x, xs);
    dim3 tg(32, 32), tb(32, 8);
    split_w_t_kernel<<<tg, tb>>>(wq, ws);
    split_w_t_kernel<<<tg, tb>>>(wk, ws + (size_t)D_ * K2_);
    split_w_t_kernel<<<tg, tb>>>(wv, ws + (size_t)2 * D_ * K2_);
    split_w_t_kernel<<<tg, tb>>>(wo, wos);

    // Fused QKV projections (z selects Q/K/V; 1/sqrt(DH) folded into Q)
    dim3 gq(D_ / 128, M_ / 128, 3);
    hgemm<1><<<gq, 256, GEMM_SMEM>>>(
        (const __half*)xs, (const __half*)ws,
        bq, bk, bv, qp, kp, vp);

    // Attention (HMMA)
    attn_mma<<<dim3(S_ / QT_, H_, B_), 256, ATT_SMEM>>>(qp, kp, vp, aos);

    // Output projection
    dim3 go(D_ / 128, M_ / 128, 1);
    hgemm<0><<<go, 256, GEMM_SMEM>>>(
        (const __half*)aos, (const __half*)wos,
        bo, bo, bo, out, out, out);
}